// round 1
// baseline (speedup 1.0000x reference)
#include <cuda_runtime.h>
#include <math.h>

// ---- problem dims ----
#define DM   512        // d_model
#define DI   1024       // d_inner
#define DS   64         // d_state
#define DTR  32         // dt_rank
#define NB   2
#define LSEQ 1024
#define NTOK (NB*LSEQ)  // 2048
#define XDBW (DTR + 2*DS)  // 160

// ---- scratch (no cudaMalloc allowed) ----
__device__ float g_xn[NTOK*DM];
__device__ float g_xz[(size_t)NTOK*2*DI];
__device__ float g_x[(size_t)NTOK*DI];
__device__ float g_xdb[(size_t)NTOK*XDBW];
__device__ float g_delta[(size_t)NTOK*DI];
__device__ float g_y[(size_t)NTOK*DI];
__device__ float g_yv[(size_t)NTOK*DI];

// =====================================================================
// LayerNorm: one block per token, 128 threads x float4
// =====================================================================
__global__ void ln_kernel(const float* __restrict__ frames,
                          const float* __restrict__ gamma,
                          const float* __restrict__ beta,
                          float* __restrict__ xn) {
    int m = blockIdx.x;
    int tid = threadIdx.x;              // 128 threads, 4 floats each = 512
    const float4* r = (const float4*)(frames + (size_t)m * DM);
    float4 v = r[tid];
    float s  = v.x + v.y + v.z + v.w;
    float sq = v.x*v.x + v.y*v.y + v.z*v.z + v.w*v.w;
    #pragma unroll
    for (int o = 16; o; o >>= 1) {
        s  += __shfl_xor_sync(~0u, s,  o);
        sq += __shfl_xor_sync(~0u, sq, o);
    }
    __shared__ float ss[4], ssq[4];
    int w = tid >> 5, lane = tid & 31;
    if (lane == 0) { ss[w] = s; ssq[w] = sq; }
    __syncthreads();
    s  = ss[0] + ss[1] + ss[2] + ss[3];
    sq = ssq[0] + ssq[1] + ssq[2] + ssq[3];
    float mean = s * (1.f / DM);
    float var  = sq * (1.f / DM) - mean * mean;
    float rstd = rsqrtf(var + 1e-5f);
    float4 g  = ((const float4*)gamma)[tid];
    float4 bt = ((const float4*)beta)[tid];
    float4 o;
    o.x = (v.x - mean) * rstd * g.x + bt.x;
    o.y = (v.y - mean) * rstd * g.y + bt.y;
    o.z = (v.z - mean) * rstd * g.z + bt.z;
    o.w = (v.w - mean) * rstd * g.w + bt.w;
    ((float4*)(xn + (size_t)m * DM))[tid] = o;
}

// =====================================================================
// Templated fp32 tiled SGEMM with fused epilogues.
// A: MxK row-major (lda), B: KxN row-major (ldb), C: MxN row-major (ldc).
// All tile dims assumed to divide M/N/K (true for this problem).
// =====================================================================
#define EPI_NONE     0
#define EPI_SOFTPLUS 1   // C = softplus(acc + aux[col])
#define EPI_RESID    2   // C = acc + aux[row*ldc+col]

template<int BM, int BN, int BK, int TM, int TN, int EPI>
__global__ void sgemm_kernel(const float* __restrict__ A,
                             const float* __restrict__ B,
                             float* __restrict__ C,
                             int M, int N, int K,
                             int lda, int ldb, int ldc,
                             const float* __restrict__ aux) {
    constexpr int THREADS = (BM / TM) * (BN / TN);
    __shared__ float As[BK][BM + 4];
    __shared__ float Bs[BK][BN];
    int tid = threadIdx.x;
    int m0 = blockIdx.y * BM;
    int n0 = blockIdx.x * BN;
    int tx = tid % (BN / TN);
    int ty = tid / (BN / TN);

    float acc[TM][TN];
    #pragma unroll
    for (int i = 0; i < TM; i++)
        #pragma unroll
        for (int j = 0; j < TN; j++) acc[i][j] = 0.f;

    for (int k0 = 0; k0 < K; k0 += BK) {
        // load A tile (transposed into As[k][m])
        #pragma unroll
        for (int idx = tid * 4; idx < BM * BK; idx += THREADS * 4) {
            int i = idx / BK, j = idx % BK;
            float4 v = *(const float4*)(A + (size_t)(m0 + i) * lda + k0 + j);
            As[j + 0][i] = v.x; As[j + 1][i] = v.y;
            As[j + 2][i] = v.z; As[j + 3][i] = v.w;
        }
        // load B tile
        #pragma unroll
        for (int idx = tid * 4; idx < BK * BN; idx += THREADS * 4) {
            int i = idx / BN, j = idx % BN;
            *(float4*)&Bs[i][j] = *(const float4*)(B + (size_t)(k0 + i) * ldb + n0 + j);
        }
        __syncthreads();
        #pragma unroll
        for (int kk = 0; kk < BK; kk++) {
            float ra[TM], rb[TN];
            #pragma unroll
            for (int i = 0; i < TM; i++) ra[i] = As[kk][ty * TM + i];
            #pragma unroll
            for (int j = 0; j < TN; j++) rb[j] = Bs[kk][tx * TN + j];
            #pragma unroll
            for (int i = 0; i < TM; i++)
                #pragma unroll
                for (int j = 0; j < TN; j++) acc[i][j] += ra[i] * rb[j];
        }
        __syncthreads();
    }

    #pragma unroll
    for (int i = 0; i < TM; i++) {
        size_t row = (size_t)(m0 + ty * TM + i);
        #pragma unroll
        for (int j = 0; j < TN; j++) {
            int col = n0 + tx * TN + j;
            float v = acc[i][j];
            if (EPI == EPI_SOFTPLUS) {
                v += aux[col];
                v = fmaxf(v, 0.f) + log1pf(__expf(-fabsf(v)));
            }
            if (EPI == EPI_RESID) {
                v += aux[row * ldc + col];
            }
            C[row * ldc + col] = v;
        }
    }
}

// =====================================================================
// Causal depthwise conv (d_conv=4) + bias + SiLU.
// Reads x half of xz [tok, 2*DI]; writes x [tok, DI].
// =====================================================================
__global__ void conv_silu_kernel(const float* __restrict__ xz,
                                 const float* __restrict__ cw,
                                 const float* __restrict__ cb,
                                 float* __restrict__ xo) {
    int idx = blockIdx.x * blockDim.x + threadIdx.x;   // token*DI + d
    if (idx >= NTOK * DI) return;
    int d = idx & (DI - 1);
    int token = idx >> 10;
    int t = token & (LSEQ - 1);
    float4 w = ((const float4*)cw)[d];
    const float* p = xz + (size_t)token * (2 * DI) + d;
    float acc = cb[d];
    if (t >= 3) acc += w.x * p[-3 * 2 * DI];
    if (t >= 2) acc += w.y * p[-2 * 2 * DI];
    if (t >= 1) acc += w.z * p[-1 * 2 * DI];
    acc += w.w * p[0];
    xo[idx] = acc / (1.f + __expf(-acc));   // silu
}

// =====================================================================
// Selective scan. One warp per (b, d) channel; 2 states per lane.
// B_t/C_t (shared across channels of a batch) staged in smem per chunk.
// =====================================================================
#define SCAN_WARPS 8
#define TCH 64

__global__ void scan_kernel(const float* __restrict__ delta,
                            const float* __restrict__ xconv,
                            const float* __restrict__ xdb,
                            const float* __restrict__ A_log,
                            float* __restrict__ y) {
    int b  = blockIdx.y;
    int d0 = blockIdx.x * SCAN_WARPS;
    int tid = threadIdx.x;
    int w = tid >> 5, lane = tid & 31;
    int d = d0 + w;

    __shared__ float Bs[TCH][DS];
    __shared__ float Cs[TCH][DS];
    __shared__ float ds[SCAN_WARPS][TCH];
    __shared__ float xs[SCAN_WARPS][TCH];

    float a0 = -__expf(A_log[(size_t)d * DS + lane]);
    float a1 = -__expf(A_log[(size_t)d * DS + lane + 32]);
    float h0 = 0.f, h1 = 0.f;

    for (int tc = 0; tc < LSEQ; tc += TCH) {
        __syncthreads();   // previous chunk fully consumed
        // stage B, C (float4 over state dim)
        for (int i = tid; i < TCH * (DS / 4); i += SCAN_WARPS * 32) {
            int t  = i >> 4;
            int s4 = (i & 15) << 2;
            const float* p = xdb + (size_t)(b * LSEQ + tc + t) * XDBW;
            *(float4*)&Bs[t][s4] = *(const float4*)(p + DTR + s4);
            *(float4*)&Cs[t][s4] = *(const float4*)(p + DTR + DS + s4);
        }
        // stage delta, x for this block's channels
        for (int i = tid; i < SCAN_WARPS * TCH; i += SCAN_WARPS * 32) {
            int j = i & (SCAN_WARPS - 1);
            int t = i >> 3;
            size_t off = (size_t)(b * LSEQ + tc + t) * DI + d0 + j;
            ds[j][t] = delta[off];
            xs[j][t] = xconv[off];
        }
        __syncthreads();

        #pragma unroll 4
        for (int i = 0; i < TCH; i++) {
            float dt = ds[w][i];
            float xt = xs[w][i];
            float dx = dt * xt;
            float dA0 = __expf(dt * a0);
            float dA1 = __expf(dt * a1);
            h0 = h0 * dA0 + dx * Bs[i][lane];
            h1 = h1 * dA1 + dx * Bs[i][lane + 32];
            float p = h0 * Cs[i][lane] + h1 * Cs[i][lane + 32];
            p += __shfl_xor_sync(~0u, p, 16);
            p += __shfl_xor_sync(~0u, p, 8);
            p += __shfl_xor_sync(~0u, p, 4);
            p += __shfl_xor_sync(~0u, p, 2);
            p += __shfl_xor_sync(~0u, p, 1);
            if (lane == 0)
                y[(size_t)(b * LSEQ + tc + i) * DI + d] = p;
        }
    }
}

// =====================================================================
// Gated epilogue: yv = (y + x*D) * silu(z)
// =====================================================================
__global__ void yv_kernel(const float* __restrict__ y,
                          const float* __restrict__ x,
                          const float* __restrict__ xz,
                          const float* __restrict__ Dv,
                          float* __restrict__ yv) {
    int idx = blockIdx.x * blockDim.x + threadIdx.x;
    if (idx >= NTOK * DI) return;
    int d = idx & (DI - 1);
    int token = idx >> 10;
    float z = xz[(size_t)token * (2 * DI) + DI + d];
    float sz = z / (1.f + __expf(-z));
    yv[idx] = (y[idx] + x[idx] * Dv[d]) * sz;
}

// =====================================================================
// launch
// =====================================================================
extern "C" void kernel_launch(void* const* d_in, const int* in_sizes, int n_in,
                              void* d_out, int out_size) {
    const float* frames = (const float*)d_in[0];
    const float* gamma  = (const float*)d_in[1];
    const float* beta   = (const float*)d_in[2];
    const float* W_in   = (const float*)d_in[3];
    const float* conv_w = (const float*)d_in[4];
    const float* conv_b = (const float*)d_in[5];
    const float* W_x    = (const float*)d_in[6];
    const float* W_dt   = (const float*)d_in[7];
    const float* b_dt   = (const float*)d_in[8];
    const float* A_log  = (const float*)d_in[9];
    const float* Dv     = (const float*)d_in[10];
    const float* W_out  = (const float*)d_in[11];
    float* out = (float*)d_out;

    float *xn, *xz, *x, *xdb, *delta, *y, *yv;
    cudaGetSymbolAddress((void**)&xn,    g_xn);
    cudaGetSymbolAddress((void**)&xz,    g_xz);
    cudaGetSymbolAddress((void**)&x,     g_x);
    cudaGetSymbolAddress((void**)&xdb,   g_xdb);
    cudaGetSymbolAddress((void**)&delta, g_delta);
    cudaGetSymbolAddress((void**)&y,     g_y);
    cudaGetSymbolAddress((void**)&yv,    g_yv);

    // 1. LayerNorm
    ln_kernel<<<NTOK, 128>>>(frames, gamma, beta, xn);

    // 2. in_proj: xz = xn @ W_in   (2048 x 512 x 2048)
    sgemm_kernel<128,128,16,8,8,EPI_NONE>
        <<<dim3(2*DI/128, NTOK/128), 256>>>(xn, W_in, xz,
            NTOK, 2*DI, DM, DM, 2*DI, 2*DI, nullptr);

    // 3. causal conv + silu
    conv_silu_kernel<<<(NTOK*DI)/256, 256>>>(xz, conv_w, conv_b, x);

    // 4. xdb = x @ W_x   (2048 x 1024 x 160)
    sgemm_kernel<64,32,32,4,4,EPI_NONE>
        <<<dim3(XDBW/32, NTOK/64), 128>>>(x, W_x, xdb,
            NTOK, XDBW, DI, DI, XDBW, XDBW, nullptr);

    // 5. delta = softplus(xdb[:, :32] @ W_dt + b_dt)   (2048 x 32 x 1024)
    sgemm_kernel<64,64,16,4,4,EPI_SOFTPLUS>
        <<<dim3(DI/64, NTOK/64), 256>>>(xdb, W_dt, delta,
            NTOK, DI, DTR, XDBW, DI, DI, b_dt);

    // 6. selective scan
    scan_kernel<<<dim3(DI/SCAN_WARPS, NB), SCAN_WARPS*32>>>(delta, x, xdb, A_log, y);

    // 7. gated epilogue
    yv_kernel<<<(NTOK*DI)/256, 256>>>(y, x, xz, Dv, yv);

    // 8. out_proj + residual: out = yv @ W_out + frames   (2048 x 1024 x 512)
    sgemm_kernel<128,64,16,8,4,EPI_RESID>
        <<<dim3(DM/64, NTOK/128), 256>>>(yv, W_out, out,
            NTOK, DM, DI, DI, DM, DM, frames);
}

// round 2
// speedup vs baseline: 1.2531x; 1.2531x over previous
#include <cuda_runtime.h>
#include <math.h>
#include <stdint.h>

// ---- problem dims ----
#define DM   512        // d_model
#define DI   1024       // d_inner
#define DS   64         // d_state
#define DTR  32         // dt_rank
#define NB   2
#define LSEQ 1024
#define NTOK (NB*LSEQ)  // 2048
#define XDBW (DTR + 2*DS)  // 160

// ---- scratch (no cudaMalloc allowed) ----
__device__ float g_xn[NTOK*DM];
__device__ float g_xz[(size_t)NTOK*2*DI];
__device__ float g_x[(size_t)NTOK*DI];
__device__ float g_xdb[(size_t)NTOK*XDBW];
__device__ float g_delta[(size_t)NTOK*DI];
__device__ float g_y[(size_t)NTOK*DI];
__device__ float g_yv[(size_t)NTOK*DI];

// =====================================================================
// LayerNorm: one block per token, 128 threads x float4
// =====================================================================
__global__ void ln_kernel(const float* __restrict__ frames,
                          const float* __restrict__ gamma,
                          const float* __restrict__ beta,
                          float* __restrict__ xn) {
    int m = blockIdx.x;
    int tid = threadIdx.x;
    const float4* r = (const float4*)(frames + (size_t)m * DM);
    float4 v = r[tid];
    float s  = v.x + v.y + v.z + v.w;
    float sq = v.x*v.x + v.y*v.y + v.z*v.z + v.w*v.w;
    #pragma unroll
    for (int o = 16; o; o >>= 1) {
        s  += __shfl_xor_sync(~0u, s,  o);
        sq += __shfl_xor_sync(~0u, sq, o);
    }
    __shared__ float ss[4], ssq[4];
    int w = tid >> 5, lane = tid & 31;
    if (lane == 0) { ss[w] = s; ssq[w] = sq; }
    __syncthreads();
    s  = ss[0] + ss[1] + ss[2] + ss[3];
    sq = ssq[0] + ssq[1] + ssq[2] + ssq[3];
    float mean = s * (1.f / DM);
    float var  = sq * (1.f / DM) - mean * mean;
    float rstd = rsqrtf(var + 1e-5f);
    float4 g  = ((const float4*)gamma)[tid];
    float4 bt = ((const float4*)beta)[tid];
    float4 o;
    o.x = (v.x - mean) * rstd * g.x + bt.x;
    o.y = (v.y - mean) * rstd * g.y + bt.y;
    o.z = (v.z - mean) * rstd * g.z + bt.z;
    o.w = (v.w - mean) * rstd * g.w + bt.w;
    ((float4*)(xn + (size_t)m * DM))[tid] = o;
}

// =====================================================================
// TF32 tensor-core GEMM (mma.sync.m16n8k8).
// A: MxK row-major, B: KxN row-major, C: MxN row-major.
// Warp tile 32x32 (2x4 tiles of m16n8). BK=16.
// =====================================================================
#define EPI_NONE     0
#define EPI_SOFTPLUS 1   // C = softplus(acc + aux[col])
#define EPI_RESID    2   // C = acc + aux[row*ldc+col]

__device__ __forceinline__ void mma_tf32(float c[4], const uint32_t a[4], const uint32_t b[2]) {
    asm volatile(
        "mma.sync.aligned.m16n8k8.row.col.f32.tf32.tf32.f32 "
        "{%0,%1,%2,%3}, {%4,%5,%6,%7}, {%8,%9}, {%0,%1,%2,%3};"
        : "+f"(c[0]), "+f"(c[1]), "+f"(c[2]), "+f"(c[3])
        : "r"(a[0]), "r"(a[1]), "r"(a[2]), "r"(a[3]), "r"(b[0]), "r"(b[1]));
}

template<int BM, int BN, int EPI>
__global__ void tgemm_kernel(const float* __restrict__ A,
                             const float* __restrict__ B,
                             float* __restrict__ C,
                             int M, int N, int K,
                             int lda, int ldb, int ldc,
                             const float* __restrict__ aux) {
    constexpr int WM = BM / 32;        // warps along M
    constexpr int WN = BN / 32;        // warps along N
    constexpr int NW = WM * WN;
    constexpr int THREADS = NW * 32;
    constexpr int BK = 16;
    constexpr int AS = BK + 4;         // 20: conflict-free A frag reads
    constexpr int BS = BN + 8;         // ≡8 mod 32: conflict-free B frag reads

    __shared__ float Asm[BM][AS];
    __shared__ float Bsm[BK][BS];

    int tid = threadIdx.x, lane = tid & 31, wid = tid >> 5;
    int wm = wid % WM, wn = wid / WM;
    int m0 = blockIdx.y * BM, n0 = blockIdx.x * BN;
    int wrow = wm * 32, wcol = wn * 32;
    int g = lane >> 2, tg = lane & 3;

    float acc[2][4][4];
    #pragma unroll
    for (int a = 0; a < 2; a++)
        #pragma unroll
        for (int b = 0; b < 4; b++)
            #pragma unroll
            for (int c = 0; c < 4; c++) acc[a][b][c] = 0.f;

    for (int k0 = 0; k0 < K; k0 += BK) {
        // A tile: BM x 16 (float4 per thread-iter)
        #pragma unroll
        for (int i = tid; i < BM * 4; i += THREADS) {
            int r = i >> 2, c = (i & 3) << 2;
            float4 v = *(const float4*)(A + (size_t)(m0 + r) * lda + k0 + c);
            *(float4*)&Asm[r][c] = v;
        }
        // B tile: 16 x BN
        #pragma unroll
        for (int i = tid; i < 16 * (BN / 4); i += THREADS) {
            int r = i / (BN / 4), c = (i % (BN / 4)) << 2;
            float4 v = *(const float4*)(B + (size_t)(k0 + r) * ldb + n0 + c);
            *(float4*)&Bsm[r][c] = v;
        }
        __syncthreads();
        #pragma unroll
        for (int ks = 0; ks < 2; ks++) {
            int kb = ks * 8;
            uint32_t af[2][4], bf[4][2];
            #pragma unroll
            for (int mt = 0; mt < 2; mt++) {
                int r = wrow + mt * 16;
                af[mt][0] = __float_as_uint(Asm[r + g][kb + tg]);
                af[mt][1] = __float_as_uint(Asm[r + 8 + g][kb + tg]);
                af[mt][2] = __float_as_uint(Asm[r + g][kb + 4 + tg]);
                af[mt][3] = __float_as_uint(Asm[r + 8 + g][kb + 4 + tg]);
            }
            #pragma unroll
            for (int nt = 0; nt < 4; nt++) {
                int c = wcol + nt * 8 + g;
                bf[nt][0] = __float_as_uint(Bsm[kb + tg][c]);
                bf[nt][1] = __float_as_uint(Bsm[kb + 4 + tg][c]);
            }
            #pragma unroll
            for (int mt = 0; mt < 2; mt++)
                #pragma unroll
                for (int nt = 0; nt < 4; nt++)
                    mma_tf32(acc[mt][nt], af[mt], bf[nt]);
        }
        __syncthreads();
    }

    // epilogue
    #pragma unroll
    for (int mt = 0; mt < 2; mt++) {
        #pragma unroll
        for (int nt = 0; nt < 4; nt++) {
            int row0 = m0 + wrow + mt * 16 + g;
            int col  = n0 + wcol + nt * 8 + tg * 2;
            #pragma unroll
            for (int h = 0; h < 2; h++) {
                size_t row = row0 + h * 8;
                float v0 = acc[mt][nt][h * 2 + 0];
                float v1 = acc[mt][nt][h * 2 + 1];
                if (EPI == EPI_SOFTPLUS) {
                    v0 += aux[col];     v1 += aux[col + 1];
                    v0 = fmaxf(v0, 0.f) + log1pf(__expf(-fabsf(v0)));
                    v1 = fmaxf(v1, 0.f) + log1pf(__expf(-fabsf(v1)));
                }
                if (EPI == EPI_RESID) {
                    v0 += aux[row * ldc + col];
                    v1 += aux[row * ldc + col + 1];
                }
                float2 o = make_float2(v0, v1);
                *(float2*)(C + row * ldc + col) = o;
            }
        }
    }
}

// =====================================================================
// Causal depthwise conv (d_conv=4) + bias + SiLU.
// =====================================================================
__global__ void conv_silu_kernel(const float* __restrict__ xz,
                                 const float* __restrict__ cw,
                                 const float* __restrict__ cb,
                                 float* __restrict__ xo) {
    int idx = blockIdx.x * blockDim.x + threadIdx.x;
    if (idx >= NTOK * DI) return;
    int d = idx & (DI - 1);
    int token = idx >> 10;
    int t = token & (LSEQ - 1);
    float4 w = ((const float4*)cw)[d];
    const float* p = xz + (size_t)token * (2 * DI) + d;
    float acc = cb[d];
    if (t >= 3) acc += w.x * p[-3 * 2 * DI];
    if (t >= 2) acc += w.y * p[-2 * 2 * DI];
    if (t >= 1) acc += w.z * p[-1 * 2 * DI];
    acc += w.w * p[0];
    xo[idx] = acc / (1.f + __expf(-acc));
}

// =====================================================================
// Selective scan. One warp per (b, d) channel; 2 states per lane.
// =====================================================================
#define SCAN_WARPS 8
#define TCH 64

__global__ void scan_kernel(const float* __restrict__ delta,
                            const float* __restrict__ xconv,
                            const float* __restrict__ xdb,
                            const float* __restrict__ A_log,
                            float* __restrict__ y) {
    int b  = blockIdx.y;
    int d0 = blockIdx.x * SCAN_WARPS;
    int tid = threadIdx.x;
    int w = tid >> 5, lane = tid & 31;
    int d = d0 + w;

    __shared__ float Bs[TCH][DS];
    __shared__ float Cs[TCH][DS];
    __shared__ float ds[SCAN_WARPS][TCH];
    __shared__ float xs[SCAN_WARPS][TCH];

    float a0 = -__expf(A_log[(size_t)d * DS + lane]);
    float a1 = -__expf(A_log[(size_t)d * DS + lane + 32]);
    float h0 = 0.f, h1 = 0.f;

    for (int tc = 0; tc < LSEQ; tc += TCH) {
        __syncthreads();
        for (int i = tid; i < TCH * (DS / 4); i += SCAN_WARPS * 32) {
            int t  = i >> 4;
            int s4 = (i & 15) << 2;
            const float* p = xdb + (size_t)(b * LSEQ + tc + t) * XDBW;
            *(float4*)&Bs[t][s4] = *(const float4*)(p + DTR + s4);
            *(float4*)&Cs[t][s4] = *(const float4*)(p + DTR + DS + s4);
        }
        for (int i = tid; i < SCAN_WARPS * TCH; i += SCAN_WARPS * 32) {
            int j = i & (SCAN_WARPS - 1);
            int t = i >> 3;
            size_t off = (size_t)(b * LSEQ + tc + t) * DI + d0 + j;
            ds[j][t] = delta[off];
            xs[j][t] = xconv[off];
        }
        __syncthreads();

        #pragma unroll 4
        for (int i = 0; i < TCH; i++) {
            float dt = ds[w][i];
            float xt = xs[w][i];
            float dx = dt * xt;
            float dA0 = __expf(dt * a0);
            float dA1 = __expf(dt * a1);
            h0 = h0 * dA0 + dx * Bs[i][lane];
            h1 = h1 * dA1 + dx * Bs[i][lane + 32];
            float p = h0 * Cs[i][lane] + h1 * Cs[i][lane + 32];
            p += __shfl_xor_sync(~0u, p, 16);
            p += __shfl_xor_sync(~0u, p, 8);
            p += __shfl_xor_sync(~0u, p, 4);
            p += __shfl_xor_sync(~0u, p, 2);
            p += __shfl_xor_sync(~0u, p, 1);
            if (lane == 0)
                y[(size_t)(b * LSEQ + tc + i) * DI + d] = p;
        }
    }
}

// =====================================================================
// Gated epilogue: yv = (y + x*D) * silu(z)
// =====================================================================
__global__ void yv_kernel(const float* __restrict__ y,
                          const float* __restrict__ x,
                          const float* __restrict__ xz,
                          const float* __restrict__ Dv,
                          float* __restrict__ yv) {
    int idx = blockIdx.x * blockDim.x + threadIdx.x;
    if (idx >= NTOK * DI) return;
    int d = idx & (DI - 1);
    int token = idx >> 10;
    float z = xz[(size_t)token * (2 * DI) + DI + d];
    float sz = z / (1.f + __expf(-z));
    yv[idx] = (y[idx] + x[idx] * Dv[d]) * sz;
}

// =====================================================================
// launch
// =====================================================================
extern "C" void kernel_launch(void* const* d_in, const int* in_sizes, int n_in,
                              void* d_out, int out_size) {
    const float* frames = (const float*)d_in[0];
    const float* gamma  = (const float*)d_in[1];
    const float* beta   = (const float*)d_in[2];
    const float* W_in   = (const float*)d_in[3];
    const float* conv_w = (const float*)d_in[4];
    const float* conv_b = (const float*)d_in[5];
    const float* W_x    = (const float*)d_in[6];
    const float* W_dt   = (const float*)d_in[7];
    const float* b_dt   = (const float*)d_in[8];
    const float* A_log  = (const float*)d_in[9];
    const float* Dv     = (const float*)d_in[10];
    const float* W_out  = (const float*)d_in[11];
    float* out = (float*)d_out;

    float *xn, *xz, *x, *xdb, *delta, *y, *yv;
    cudaGetSymbolAddress((void**)&xn,    g_xn);
    cudaGetSymbolAddress((void**)&xz,    g_xz);
    cudaGetSymbolAddress((void**)&x,     g_x);
    cudaGetSymbolAddress((void**)&xdb,   g_xdb);
    cudaGetSymbolAddress((void**)&delta, g_delta);
    cudaGetSymbolAddress((void**)&y,     g_y);
    cudaGetSymbolAddress((void**)&yv,    g_yv);

    // 1. LayerNorm
    ln_kernel<<<NTOK, 128>>>(frames, gamma, beta, xn);

    // 2. in_proj: xz = xn @ W_in  (2048 x 2048 x 512), tf32 MMA
    tgemm_kernel<128,64,EPI_NONE>
        <<<dim3(2*DI/64, NTOK/128), 256>>>(xn, W_in, xz,
            NTOK, 2*DI, DM, DM, 2*DI, 2*DI, nullptr);

    // 3. causal conv + silu
    conv_silu_kernel<<<(NTOK*DI)/256, 256>>>(xz, conv_w, conv_b, x);

    // 4. xdb = x @ W_x  (2048 x 160 x 1024), tf32 MMA, BN=32 (160%32==0)
    tgemm_kernel<128,32,EPI_NONE>
        <<<dim3(XDBW/32, NTOK/128), 128>>>(x, W_x, xdb,
            NTOK, XDBW, DI, DI, XDBW, XDBW, nullptr);

    // 5. delta = softplus(xdb[:, :32] @ W_dt + b_dt)  (2048 x 1024 x 32)
    tgemm_kernel<128,64,EPI_SOFTPLUS>
        <<<dim3(DI/64, NTOK/128), 256>>>(xdb, W_dt, delta,
            NTOK, DI, DTR, XDBW, DI, DI, b_dt);

    // 6. selective scan
    scan_kernel<<<dim3(DI/SCAN_WARPS, NB), SCAN_WARPS*32>>>(delta, x, xdb, A_log, y);

    // 7. gated epilogue
    yv_kernel<<<(NTOK*DI)/256, 256>>>(y, x, xz, Dv, yv);

    // 8. out_proj + residual: out = yv @ W_out + frames  (2048 x 512 x 1024)
    tgemm_kernel<128,64,EPI_RESID>
        <<<dim3(DM/64, NTOK/128), 256>>>(yv, W_out, out,
            NTOK, DM, DI, DI, DM, DM, frames);
}

// round 3
// speedup vs baseline: 1.3523x; 1.0792x over previous
#include <cuda_runtime.h>
#include <math.h>
#include <stdint.h>

// ---- problem dims ----
#define DM   512
#define DI   1024
#define DS   64
#define DTR  32
#define NB   2
#define LSEQ 1024
#define NTOK (NB*LSEQ)
#define XDBW (DTR + 2*DS)   // 160
#define SPLITK_WX 4

// ---- scratch ----
__device__ float g_xn[NTOK*DM];
__device__ float g_xz[(size_t)NTOK*2*DI];
__device__ float g_x[(size_t)NTOK*DI];
__device__ float g_xdb[(size_t)NTOK*XDBW];
__device__ float g_xdb_part[(size_t)SPLITK_WX*NTOK*XDBW];
__device__ float g_delta[(size_t)NTOK*DI];
__device__ float g_yv[(size_t)NTOK*DI];

// =====================================================================
// cp.async helpers
// =====================================================================
__device__ __forceinline__ void cp_async16(uint32_t saddr, const void* gaddr) {
    asm volatile("cp.async.cg.shared.global [%0], [%1], 16;\n" :: "r"(saddr), "l"(gaddr));
}
#define CP_COMMIT() asm volatile("cp.async.commit_group;\n" ::: "memory")
#define CP_WAIT0()  asm volatile("cp.async.wait_group 0;\n" ::: "memory")

// =====================================================================
// LayerNorm
// =====================================================================
__global__ void ln_kernel(const float* __restrict__ frames,
                          const float* __restrict__ gamma,
                          const float* __restrict__ beta,
                          float* __restrict__ xn) {
    int m = blockIdx.x;
    int tid = threadIdx.x;
    const float4* r = (const float4*)(frames + (size_t)m * DM);
    float4 v = r[tid];
    float s  = v.x + v.y + v.z + v.w;
    float sq = v.x*v.x + v.y*v.y + v.z*v.z + v.w*v.w;
    #pragma unroll
    for (int o = 16; o; o >>= 1) {
        s  += __shfl_xor_sync(~0u, s,  o);
        sq += __shfl_xor_sync(~0u, sq, o);
    }
    __shared__ float ss[4], ssq[4];
    int w = tid >> 5, lane = tid & 31;
    if (lane == 0) { ss[w] = s; ssq[w] = sq; }
    __syncthreads();
    s  = ss[0] + ss[1] + ss[2] + ss[3];
    sq = ssq[0] + ssq[1] + ssq[2] + ssq[3];
    float mean = s * (1.f / DM);
    float var  = sq * (1.f / DM) - mean * mean;
    float rstd = rsqrtf(var + 1e-5f);
    float4 g  = ((const float4*)gamma)[tid];
    float4 bt = ((const float4*)beta)[tid];
    float4 o;
    o.x = (v.x - mean) * rstd * g.x + bt.x;
    o.y = (v.y - mean) * rstd * g.y + bt.y;
    o.z = (v.z - mean) * rstd * g.z + bt.z;
    o.w = (v.w - mean) * rstd * g.w + bt.w;
    ((float4*)(xn + (size_t)m * DM))[tid] = o;
}

// =====================================================================
// TF32 tensor-core GEMM, cp.async double-buffered, BK=32.
// =====================================================================
#define EPI_NONE     0
#define EPI_SOFTPLUS 1
#define EPI_RESID    2
#define EPI_PART     3   // write partial to C + blockIdx.z*M*ldc

__device__ __forceinline__ void mma_tf32(float c[4], const uint32_t a[4], const uint32_t b[2]) {
    asm volatile(
        "mma.sync.aligned.m16n8k8.row.col.f32.tf32.tf32.f32 "
        "{%0,%1,%2,%3}, {%4,%5,%6,%7}, {%8,%9}, {%0,%1,%2,%3};"
        : "+f"(c[0]), "+f"(c[1]), "+f"(c[2]), "+f"(c[3])
        : "r"(a[0]), "r"(a[1]), "r"(a[2]), "r"(a[3]), "r"(b[0]), "r"(b[1]));
}

template<int BM, int BN, int EPI, int SPLITK>
__global__ void tgemm_kernel(const float* __restrict__ A,
                             const float* __restrict__ B,
                             float* __restrict__ C,
                             int M, int N, int K,
                             int lda, int ldb, int ldc,
                             const float* __restrict__ aux) {
    constexpr int BK = 32;
    constexpr int WM = BM / 32, WN = BN / 32;
    constexpr int THREADS = WM * WN * 32;
    constexpr int AST = BK + 4;     // 36
    constexpr int BST = BN + 8;
    constexpr int ABUF = BM * AST;
    constexpr int BBUF = BK * BST;

    extern __shared__ float sm[];
    float* Asm = sm;               // [2][BM][AST]
    float* Bsm = sm + 2 * ABUF;    // [2][BK][BST]
    uint32_t sa = (uint32_t)__cvta_generic_to_shared(Asm);
    uint32_t sb = (uint32_t)__cvta_generic_to_shared(Bsm);

    int tid = threadIdx.x, lane = tid & 31, wid = tid >> 5;
    int wm = wid % WM, wn = wid / WM;
    int m0 = blockIdx.y * BM, n0 = blockIdx.x * BN;
    int wrow = wm * 32, wcol = wn * 32;
    int g = lane >> 2, tg = lane & 3;

    int kbase = (SPLITK > 1) ? blockIdx.z * (K / SPLITK) : 0;
    int kcnt  = (K / SPLITK) / BK;

    float acc[2][4][4];
    #pragma unroll
    for (int a = 0; a < 2; a++)
        #pragma unroll
        for (int b = 0; b < 4; b++)
            #pragma unroll
            for (int c = 0; c < 4; c++) acc[a][b][c] = 0.f;

    auto loadA = [&](int kt, int buf) {
        const float* Ap = A + (size_t)m0 * lda + kbase + kt * BK;
        #pragma unroll
        for (int i = tid; i < BM * (BK / 4); i += THREADS) {
            int r = i / (BK / 4), c = (i % (BK / 4)) * 4;
            cp_async16(sa + (uint32_t)(buf * ABUF + r * AST + c) * 4,
                       Ap + (size_t)r * lda + c);
        }
    };
    auto loadB = [&](int kt, int buf) {
        const float* Bp = B + (size_t)(kbase + kt * BK) * ldb + n0;
        #pragma unroll
        for (int i = tid; i < BK * (BN / 4); i += THREADS) {
            int r = i / (BN / 4), c = (i % (BN / 4)) * 4;
            cp_async16(sb + (uint32_t)(buf * BBUF + r * BST + c) * 4,
                       Bp + (size_t)r * ldb + c);
        }
    };

    loadA(0, 0); loadB(0, 0); CP_COMMIT();

    for (int kt = 0; kt < kcnt; kt++) {
        CP_WAIT0();
        __syncthreads();
        if (kt + 1 < kcnt) {
            int nb = (kt + 1) & 1;
            loadA(kt + 1, nb); loadB(kt + 1, nb); CP_COMMIT();
        }
        int cb = kt & 1;
        const float* Ab = Asm + cb * ABUF;
        const float* Bb = Bsm + cb * BBUF;
        #pragma unroll
        for (int ks = 0; ks < 4; ks++) {
            int kb = ks * 8;
            uint32_t af[2][4], bf[4][2];
            #pragma unroll
            for (int mt = 0; mt < 2; mt++) {
                int r = wrow + mt * 16;
                af[mt][0] = __float_as_uint(Ab[(r + g)     * AST + kb + tg]);
                af[mt][1] = __float_as_uint(Ab[(r + 8 + g) * AST + kb + tg]);
                af[mt][2] = __float_as_uint(Ab[(r + g)     * AST + kb + 4 + tg]);
                af[mt][3] = __float_as_uint(Ab[(r + 8 + g) * AST + kb + 4 + tg]);
            }
            #pragma unroll
            for (int nt = 0; nt < 4; nt++) {
                int c = wcol + nt * 8 + g;
                bf[nt][0] = __float_as_uint(Bb[(kb + tg)     * BST + c]);
                bf[nt][1] = __float_as_uint(Bb[(kb + 4 + tg) * BST + c]);
            }
            #pragma unroll
            for (int mt = 0; mt < 2; mt++)
                #pragma unroll
                for (int nt = 0; nt < 4; nt++)
                    mma_tf32(acc[mt][nt], af[mt], bf[nt]);
        }
        __syncthreads();
    }

    float* Cw = C;
    if (EPI == EPI_PART) Cw = C + (size_t)blockIdx.z * M * ldc;

    #pragma unroll
    for (int mt = 0; mt < 2; mt++) {
        #pragma unroll
        for (int nt = 0; nt < 4; nt++) {
            int row0 = m0 + wrow + mt * 16 + g;
            int col  = n0 + wcol + nt * 8 + tg * 2;
            #pragma unroll
            for (int h = 0; h < 2; h++) {
                size_t row = row0 + h * 8;
                float v0 = acc[mt][nt][h * 2 + 0];
                float v1 = acc[mt][nt][h * 2 + 1];
                if (EPI == EPI_SOFTPLUS) {
                    v0 += aux[col];     v1 += aux[col + 1];
                    v0 = fmaxf(v0, 0.f) + log1pf(__expf(-fabsf(v0)));
                    v1 = fmaxf(v1, 0.f) + log1pf(__expf(-fabsf(v1)));
                }
                if (EPI == EPI_RESID) {
                    v0 += aux[row * ldc + col];
                    v1 += aux[row * ldc + col + 1];
                }
                *(float2*)(Cw + row * ldc + col) = make_float2(v0, v1);
            }
        }
    }
}

// =====================================================================
// reduce 4 split-K partials
// =====================================================================
__global__ void reduce4_kernel(const float4* __restrict__ part,
                               float4* __restrict__ out, int n4) {
    int i = blockIdx.x * blockDim.x + threadIdx.x;
    if (i >= n4) return;
    float4 a = part[i], b = part[i + n4], c = part[i + 2 * n4], d = part[i + 3 * n4];
    float4 o;
    o.x = a.x + b.x + c.x + d.x;
    o.y = a.y + b.y + c.y + d.y;
    o.z = a.z + b.z + c.z + d.z;
    o.w = a.w + b.w + c.w + d.w;
    out[i] = o;
}

// =====================================================================
// Causal depthwise conv + bias + SiLU
// =====================================================================
__global__ void conv_silu_kernel(const float* __restrict__ xz,
                                 const float* __restrict__ cw,
                                 const float* __restrict__ cb,
                                 float* __restrict__ xo) {
    int idx = blockIdx.x * blockDim.x + threadIdx.x;
    if (idx >= NTOK * DI) return;
    int d = idx & (DI - 1);
    int token = idx >> 10;
    int t = token & (LSEQ - 1);
    float4 w = ((const float4*)cw)[d];
    const float* p = xz + (size_t)token * (2 * DI) + d;
    float acc = cb[d];
    if (t >= 3) acc += w.x * p[-3 * 2 * DI];
    if (t >= 2) acc += w.y * p[-2 * 2 * DI];
    if (t >= 1) acc += w.z * p[-1 * 2 * DI];
    acc += w.w * p[0];
    xo[idx] = acc / (1.f + __expf(-acc));
}

// =====================================================================
// Selective scan + fused gated epilogue:
// yv = (scan_y + x*D) * silu(z), written directly.
// =====================================================================
#define SCAN_WARPS 8
#define TCH 64

__global__ void scan_kernel(const float* __restrict__ delta,
                            const float* __restrict__ xconv,
                            const float* __restrict__ xdb,
                            const float* __restrict__ xz,
                            const float* __restrict__ A_log,
                            const float* __restrict__ Dv,
                            float* __restrict__ yv) {
    int b  = blockIdx.y;
    int d0 = blockIdx.x * SCAN_WARPS;
    int tid = threadIdx.x;
    int w = tid >> 5, lane = tid & 31;
    int d = d0 + w;

    __shared__ float Bs[TCH][DS];
    __shared__ float Cs[TCH][DS];
    __shared__ float ds[SCAN_WARPS][TCH];
    __shared__ float xs[SCAN_WARPS][TCH];
    __shared__ float zs[SCAN_WARPS][TCH];

    float a0 = -__expf(A_log[(size_t)d * DS + lane]);
    float a1 = -__expf(A_log[(size_t)d * DS + lane + 32]);
    float Dval = Dv[d];
    float h0 = 0.f, h1 = 0.f;

    for (int tc = 0; tc < LSEQ; tc += TCH) {
        __syncthreads();
        for (int i = tid; i < TCH * (DS / 4); i += SCAN_WARPS * 32) {
            int t  = i >> 4;
            int s4 = (i & 15) << 2;
            const float* p = xdb + (size_t)(b * LSEQ + tc + t) * XDBW;
            *(float4*)&Bs[t][s4] = *(const float4*)(p + DTR + s4);
            *(float4*)&Cs[t][s4] = *(const float4*)(p + DTR + DS + s4);
        }
        for (int i = tid; i < SCAN_WARPS * TCH; i += SCAN_WARPS * 32) {
            int j = i & (SCAN_WARPS - 1);
            int t = i >> 3;
            size_t tok = (size_t)(b * LSEQ + tc + t);
            ds[j][t] = delta[tok * DI + d0 + j];
            xs[j][t] = xconv[tok * DI + d0 + j];
            zs[j][t] = xz[tok * (2 * DI) + DI + d0 + j];
        }
        __syncthreads();

        #pragma unroll 4
        for (int i = 0; i < TCH; i++) {
            float dt = ds[w][i];
            float xt = xs[w][i];
            float dx = dt * xt;
            float dA0 = __expf(dt * a0);
            float dA1 = __expf(dt * a1);
            h0 = h0 * dA0 + dx * Bs[i][lane];
            h1 = h1 * dA1 + dx * Bs[i][lane + 32];
            float p = h0 * Cs[i][lane] + h1 * Cs[i][lane + 32];
            p += __shfl_xor_sync(~0u, p, 16);
            p += __shfl_xor_sync(~0u, p, 8);
            p += __shfl_xor_sync(~0u, p, 4);
            p += __shfl_xor_sync(~0u, p, 2);
            p += __shfl_xor_sync(~0u, p, 1);
            if (lane == 0) {
                float z = zs[w][i];
                float sz = z / (1.f + __expf(-z));
                yv[(size_t)(b * LSEQ + tc + i) * DI + d] = (p + xt * Dval) * sz;
            }
        }
    }
}

// =====================================================================
// launch
// =====================================================================
extern "C" void kernel_launch(void* const* d_in, const int* in_sizes, int n_in,
                              void* d_out, int out_size) {
    const float* frames = (const float*)d_in[0];
    const float* gamma  = (const float*)d_in[1];
    const float* beta   = (const float*)d_in[2];
    const float* W_in   = (const float*)d_in[3];
    const float* conv_w = (const float*)d_in[4];
    const float* conv_b = (const float*)d_in[5];
    const float* W_x    = (const float*)d_in[6];
    const float* W_dt   = (const float*)d_in[7];
    const float* b_dt   = (const float*)d_in[8];
    const float* A_log  = (const float*)d_in[9];
    const float* Dv     = (const float*)d_in[10];
    const float* W_out  = (const float*)d_in[11];
    float* out = (float*)d_out;

    float *xn, *xz, *x, *xdb, *xdbp, *delta, *yv;
    cudaGetSymbolAddress((void**)&xn,    g_xn);
    cudaGetSymbolAddress((void**)&xz,    g_xz);
    cudaGetSymbolAddress((void**)&x,     g_x);
    cudaGetSymbolAddress((void**)&xdb,   g_xdb);
    cudaGetSymbolAddress((void**)&xdbp,  g_xdb_part);
    cudaGetSymbolAddress((void**)&delta, g_delta);
    cudaGetSymbolAddress((void**)&yv,    g_yv);

    // dynamic smem sizes
    constexpr int SM_IN  = (2*128*36 + 2*32*136) * 4;  // 71680 (BM128,BN128)
    constexpr int SM_WX  = (2*128*36 + 2*32*40)  * 4;  // 47104 (BM128,BN32)
    constexpr int SM_64  = (2*128*36 + 2*32*72)  * 4;  // 55296 (BM128,BN64)

    static bool attr_done = false;
    if (!attr_done) {
        cudaFuncSetAttribute((const void*)tgemm_kernel<128,128,EPI_NONE,1>,
                             cudaFuncAttributeMaxDynamicSharedMemorySize, SM_IN);
        cudaFuncSetAttribute((const void*)tgemm_kernel<128,32,EPI_PART,SPLITK_WX>,
                             cudaFuncAttributeMaxDynamicSharedMemorySize, SM_WX);
        cudaFuncSetAttribute((const void*)tgemm_kernel<128,64,EPI_SOFTPLUS,1>,
                             cudaFuncAttributeMaxDynamicSharedMemorySize, SM_64);
        cudaFuncSetAttribute((const void*)tgemm_kernel<128,64,EPI_RESID,1>,
                             cudaFuncAttributeMaxDynamicSharedMemorySize, SM_64);
        attr_done = true;
    }

    // 1. LayerNorm
    ln_kernel<<<NTOK, 128>>>(frames, gamma, beta, xn);

    // 2. in_proj: xz = xn @ W_in  (2048 x 2048 x 512)
    tgemm_kernel<128,128,EPI_NONE,1>
        <<<dim3(2*DI/128, NTOK/128), 512, SM_IN>>>(xn, W_in, xz,
            NTOK, 2*DI, DM, DM, 2*DI, 2*DI, nullptr);

    // 3. causal conv + silu
    conv_silu_kernel<<<(NTOK*DI)/256, 256>>>(xz, conv_w, conv_b, x);

    // 4. xdb = x @ W_x  (2048 x 160 x 1024), split-K=4 partials + reduce
    tgemm_kernel<128,32,EPI_PART,SPLITK_WX>
        <<<dim3(XDBW/32, NTOK/128, SPLITK_WX), 128, SM_WX>>>(x, W_x, xdbp,
            NTOK, XDBW, DI, DI, XDBW, XDBW, nullptr);
    reduce4_kernel<<<(NTOK*XDBW/4 + 255)/256, 256>>>(
        (const float4*)xdbp, (float4*)xdb, NTOK*XDBW/4);

    // 5. delta = softplus(xdb[:, :32] @ W_dt + b_dt)  (2048 x 1024 x 32)
    tgemm_kernel<128,64,EPI_SOFTPLUS,1>
        <<<dim3(DI/64, NTOK/128), 256, SM_64>>>(xdb, W_dt, delta,
            NTOK, DI, DTR, XDBW, DI, DI, b_dt);

    // 6. selective scan + fused gated epilogue
    scan_kernel<<<dim3(DI/SCAN_WARPS, NB), SCAN_WARPS*32>>>(
        delta, x, xdb, xz, A_log, Dv, yv);

    // 7. out_proj + residual
    tgemm_kernel<128,64,EPI_RESID,1>
        <<<dim3(DM/64, NTOK/128), 256, SM_64>>>(yv, W_out, out,
            NTOK, DM, DI, DI, DM, DM, frames);
}